// round 13
// baseline (speedup 1.0000x reference)
#include <cuda_runtime.h>
#include <cstdint>

#define BATCH 64
#define DDIM 384
#define NPIX (BATCH*32*32)

// ---------------- scratch ----------------
__device__ float g_y4[NPIX*4];
__device__ float g_ah[BATCH*32*1024];
__device__ float g_aw[BATCH*32*1024];
__device__ float g_T [NPIX*DDIM];
__device__ float g_mx[NPIX*DDIM];
__device__ float g_wcat[768*384];
__device__ float g_wfrag[3*48*2048];   // fragment-ordered tf32 weights
__device__ float g_bco[384];

__device__ __forceinline__ unsigned f2tf32(float f) {
    unsigned u; asm("cvt.rna.tf32.f32 %0, %1;" : "=r"(u) : "f"(f)); return u;
}
__device__ __forceinline__ unsigned long long pack2(float a) {
    unsigned long long r; asm("mov.b64 %0, {%1, %1};" : "=l"(r) : "f"(a)); return r;
}
#define FMA2(d,a,b) asm("fma.rn.f32x2 %0, %1, %2, %0;" : "+l"(d) : "l"(a), "l"(b))

// ---------------- prep ----------------
__global__ __launch_bounds__(1024) void prep_wco(const float* __restrict__ Wc,
                                                 const float* __restrict__ Wo) {
    __shared__ float sWo[32][33], sWc[32][33];
    int tx = threadIdx.x, ty = threadIdx.y;
    int o0 = blockIdx.x * 32, k0 = blockIdx.y * 32;
    float acc = 0.f;
    for (int dt = 0; dt < 12; ++dt) {
        sWo[ty][tx] = Wo[(o0 + ty)*384 + dt*32 + tx];
        sWc[ty][tx] = Wc[(dt*32 + ty)*384 + k0 + tx];
        __syncthreads();
#pragma unroll
        for (int dd = 0; dd < 32; ++dd) acc += sWo[ty][dd] * sWc[dd][tx];
        __syncthreads();
    }
    g_wcat[(k0 + tx)*384 + o0 + ty] = __uint_as_float(f2tf32(acc));
}

__global__ __launch_bounds__(1024) void prep_wot(const float* __restrict__ Wo) {
    __shared__ float s[32][33];
    int tx = threadIdx.x, ty = threadIdx.y;
    int o0 = blockIdx.x * 32, k0 = blockIdx.y * 32;
    s[ty][tx] = Wo[(o0 + ty)*384 + k0 + tx];
    __syncthreads();
    g_wcat[(384 + k0 + ty)*384 + o0 + tx] = __uint_as_float(f2tf32(s[tx][ty]));
}

__global__ void prep_bco(const float* __restrict__ Wo, const float* __restrict__ bc,
                         const float* __restrict__ bo) {
    int o = threadIdx.x;
    if (o < 384) {
        float acc = bo[o];
        for (int k = 0; k < 384; ++k) acc += Wo[o*384 + k] * bc[k];
        g_bco[o] = acc;
    }
}

// Rearrange g_wcat into per-(cblk,kt) mma-fragment order.
// slice layout: sel = (ks8*2 + h)*2 + ncol; within sel: half(2) x lane(32) x j(4)
// value = Wcat[kt*16 + ks8*8 + h*4 + tig][cblk*128 + ncol*64 + (half*4+j)*8 + gid]
__global__ __launch_bounds__(1024) void prep_frag() {
    int fidx = blockIdx.x * 1024 + threadIdx.x;   // < 3*48*2048
    int j    = fidx & 3;
    int lane = (fidx >> 2) & 31;
    int half = (fidx >> 7) & 1;
    int sel  = (fidx >> 8) & 7;
    int slice = fidx >> 11;
    int ncol = sel & 1, h = (sel >> 1) & 1, ks8 = sel >> 2;
    int kt = slice % 48, cblk = slice / 48;
    int tig = lane & 3, gid = lane >> 2;
    int k = kt*16 + ks8*8 + h*4 + tig;
    int o = cblk*128 + ncol*64 + (half*4 + j)*8 + gid;
    g_wfrag[fidx] = g_wcat[k*384 + o];
}

// ---------------- fused 1x1 convs (E=2, h & w branches) ----------------
__global__ __launch_bounds__(256) void y4_kernel(const float* __restrict__ x,
        const float* __restrict__ W1h, const float* __restrict__ b1h,
        const float* __restrict__ W1w, const float* __restrict__ b1w) {
    int lane = threadIdx.x & 31, warp = threadIdx.x >> 5;
    int dbase = lane * 12;
    float wh0[12], wh1[12], ww0[12], ww1[12];
#pragma unroll
    for (int u = 0; u < 12; ++u) {
        wh0[u] = __ldg(W1h + dbase + u);
        wh1[u] = __ldg(W1h + 384 + dbase + u);
        ww0[u] = __ldg(W1w + dbase + u);
        ww1[u] = __ldg(W1w + 384 + dbase + u);
    }
    float bh0 = __ldg(b1h), bh1 = __ldg(b1h+1), bw0 = __ldg(b1w), bw1 = __ldg(b1w+1);
    int pbase = blockIdx.x * 128 + warp * 16;
    for (int it = 0; it < 16; ++it) {
        int p = pbase + it;
        const float4* xr = (const float4*)(x + (size_t)p*384 + dbase);
        float4 v0 = xr[0], v1 = xr[1], v2 = xr[2];
        float xv[12] = {v0.x,v0.y,v0.z,v0.w, v1.x,v1.y,v1.z,v1.w, v2.x,v2.y,v2.z,v2.w};
        float s0=0.f, s1=0.f, s2=0.f, s3=0.f;
#pragma unroll
        for (int u = 0; u < 12; ++u) {
            s0 += xv[u]*wh0[u]; s1 += xv[u]*wh1[u];
            s2 += xv[u]*ww0[u]; s3 += xv[u]*ww1[u];
        }
#pragma unroll
        for (int off = 16; off; off >>= 1) {
            s0 += __shfl_xor_sync(~0u, s0, off);
            s1 += __shfl_xor_sync(~0u, s1, off);
            s2 += __shfl_xor_sync(~0u, s2, off);
            s3 += __shfl_xor_sync(~0u, s3, off);
        }
        if (lane == 0)
            *(float4*)(g_y4 + (size_t)p*4) = make_float4(s0+bh0, s1+bh1, s2+bw0, s3+bw1);
    }
}

// ---------------- grouped-conv logits + softmax ----------------
__global__ __launch_bounds__(1024) void attn_kernel(const float* __restrict__ W2,
                                                    const float* __restrict__ b2, int mode) {
    __shared__ float ys[2][32];
    int blk = blockIdx.x, b = blk >> 5, s = blk & 31, t = threadIdx.x;
    if (t < 64) {
        int e = t >> 5, q = t & 31;
        int pix = mode ? ((b*32 + s)*32 + q) : ((b*32 + q)*32 + s);
        ys[e][q] = g_y4[(size_t)pix*4 + (mode ? 2 : 0) + e];
    }
    __syncthreads();
    int i = t >> 5, j = t & 31;
    int e = i >> 4;
    int cb = ((i >> 2) * 8) & 31;
    const float* wrow = W2 + (size_t)(i*32 + j)*8;
    float l = __ldg(b2 + i*32 + j);
#pragma unroll
    for (int cc = 0; cc < 8; ++cc) l += __ldg(wrow + cc) * ys[e][cb + cc];
    float m = l;
#pragma unroll
    for (int off = 16; off; off >>= 1) m = fmaxf(m, __shfl_xor_sync(~0u, m, off));
    float ex = expf(l - m), sum = ex;
#pragma unroll
    for (int off = 16; off; off >>= 1) sum += __shfl_xor_sync(~0u, sum, off);
    (mode ? g_aw : g_ah)[(size_t)blk*1024 + i*32 + j] = ex / sum;
}

// ---------------- attention apply ----------------
__global__ __launch_bounds__(256) void apply_kernel(const float* __restrict__ x, int mode) {
    extern __shared__ float sm[];
    float* xs = sm;            // [32][384]
    float* as = sm + 32*384;   // [1024]
    int blk = blockIdx.x, b = blk >> 5, s = blk & 31, t = threadIdx.x;
    size_t rowbase, rowstride;
    if (mode == 0) { rowbase = ((size_t)b*1024 + s)*384;    rowstride = 32*384; }
    else           { rowbase = ((size_t)b*1024 + s*32)*384; rowstride = 384; }
    for (int l = t; l < 3072; l += 256) {
        int r = l / 96, c4 = l % 96;
        *(float4*)&xs[r*384 + c4*4] = *(const float4*)(x + rowbase + (size_t)r*rowstride + c4*4);
    }
    const float* attn = (mode ? g_aw : g_ah) + (size_t)blk*1024;
    for (int l = t; l < 1024; l += 256) as[l] = attn[l];
    __syncthreads();
    int w = t >> 5, lane = t & 31;
    unsigned long long acc[4][6];
#pragma unroll
    for (int ii = 0; ii < 4; ++ii)
#pragma unroll
        for (int q = 0; q < 6; ++q) acc[ii][q] = 0ull;
#pragma unroll 4
    for (int j = 0; j < 32; ++j) {
        ulonglong2 xv[3];
#pragma unroll
        for (int c = 0; c < 3; ++c)
            xv[c] = *(ulonglong2*)&xs[j*384 + (lane + 32*c)*4];
#pragma unroll
        for (int ii = 0; ii < 4; ++ii) {
            unsigned long long av = pack2(as[(w + 8*ii)*32 + j]);
#pragma unroll
            for (int c = 0; c < 3; ++c) {
                FMA2(acc[ii][2*c],   av, xv[c].x);
                FMA2(acc[ii][2*c+1], av, xv[c].y);
            }
        }
    }
#pragma unroll
    for (int ii = 0; ii < 4; ++ii) {
        int i = w + 8*ii;
#pragma unroll
        for (int c = 0; c < 3; ++c) {
            int d = (lane + 32*c)*4;
            float2 u0 = *(float2*)&acc[ii][2*c];
            float2 u1 = *(float2*)&acc[ii][2*c+1];
            if (mode == 0) {
                *(float4*)(g_T + ((size_t)(b*32 + i)*32 + s)*384 + d) =
                    make_float4(u0.x, u0.y, u1.x, u1.y);
            } else {
                size_t o = ((size_t)b*1024 + s*32 + i)*384 + d;
                float4 tv = *(const float4*)(g_T + o);
                *(float4*)(g_mx + o) =
                    make_float4(u0.x+tv.x, u0.y+tv.y, u1.x+tv.z, u1.y+tv.w);
            }
        }
    }
}

// ---------------- big GEMM: out[p][o] = sum_k [x|mx][p][k] * Wcat[k][o] + bco[o]
// BM=256, BN=128, 8 warps, warp tile 64x64. A smem stride 20 (conflict-free),
// B from fragment-ordered g_wfrag via LDS.128.
#define SA_P 20
#define MMA(d, a, b0, b1) \
    asm("mma.sync.aligned.m16n8k8.row.col.f32.tf32.tf32.f32 " \
        "{%0,%1,%2,%3}, {%4,%5,%6,%7}, {%8,%9}, {%0,%1,%2,%3};" \
        : "+f"(d[0]), "+f"(d[1]), "+f"(d[2]), "+f"(d[3]) \
        : "r"(a[0]), "r"(a[1]), "r"(a[2]), "r"(a[3]), "r"(b0), "r"(b1))

__global__ __launch_bounds__(256) void gemm_kernel(const float* __restrict__ x,
                                                   float* __restrict__ out) {
    extern __shared__ __align__(16) float gs[];
    float* sA = gs;                       // 2 * 256*SA_P
    float* sB = gs + 2*256*SA_P;          // 2 * 2048
    int t = threadIdx.x;
    int row0 = blockIdx.y * 256, cblk = blockIdx.x, col0 = cblk * 128;
    unsigned saB = (unsigned)__cvta_generic_to_shared(sA);
    unsigned sbB = (unsigned)__cvta_generic_to_shared(sB);
    auto load_stage = [&](int kt, int buf) {
        const float* Ah = (kt < 24) ? x : g_mx;
        int koff = (kt < 24) ? kt*16 : kt*16 - 384;
#pragma unroll
        for (int q = 0; q < 4; ++q) {
            int c = t + 256*q, r = c >> 2, seg = c & 3;
            const float* src = Ah + (size_t)(row0 + r)*384 + koff + seg*4;
            unsigned dst = saB + (unsigned)(buf*256*SA_P + r*SA_P + seg*4)*4u;
            asm volatile("cp.async.ca.shared.global [%0], [%1], 16;" :: "r"(dst), "l"(src));
        }
        const float* srcB = g_wfrag + ((size_t)cblk*48 + kt)*2048 + t*8;
        unsigned dstB = sbB + (unsigned)(buf*2048 + t*8)*4u;
        asm volatile("cp.async.ca.shared.global [%0], [%1], 16;" :: "r"(dstB), "l"(srcB));
        asm volatile("cp.async.ca.shared.global [%0], [%1], 16;" :: "r"(dstB+16u), "l"(srcB+4));
        asm volatile("cp.async.commit_group;" ::: "memory");
    };
    int lane = t & 31, w = t >> 5;
    int gid = lane >> 2, tig = lane & 3;
    int m0 = (w & 3) * 64, ncol = w >> 2;
    float acc[4][8][4];
#pragma unroll
    for (int mt = 0; mt < 4; ++mt)
#pragma unroll
        for (int nt = 0; nt < 8; ++nt)
#pragma unroll
            for (int q = 0; q < 4; ++q) acc[mt][nt][q] = 0.f;
    load_stage(0, 0);
    for (int kt = 0; kt < 48; ++kt) {
        int buf = kt & 1;
        if (kt + 1 < 48) {
            load_stage(kt + 1, buf ^ 1);
            asm volatile("cp.async.wait_group 1;" ::: "memory");
        } else {
            asm volatile("cp.async.wait_group 0;" ::: "memory");
        }
        __syncthreads();
        const float* A = sA + buf*256*SA_P;
        const float* Bf = sB + buf*2048;
#pragma unroll
        for (int ks8 = 0; ks8 < 2; ++ks8) {
            unsigned af[4][4];
#pragma unroll
            for (int mt = 0; mt < 4; ++mt) {
                int rm = m0 + mt*16 + gid;
                af[mt][0] = f2tf32(A[rm*SA_P     + ks8*8 + tig]);
                af[mt][1] = f2tf32(A[(rm+8)*SA_P + ks8*8 + tig]);
                af[mt][2] = f2tf32(A[rm*SA_P     + ks8*8 + tig + 4]);
                af[mt][3] = f2tf32(A[(rm+8)*SA_P + ks8*8 + tig + 4]);
            }
            int base0 = ((ks8*2 + 0)*2 + ncol)*256 + lane*4;
            int base1 = ((ks8*2 + 1)*2 + ncol)*256 + lane*4;
            float4 b0a = *(const float4*)&Bf[base0];
            float4 b0b = *(const float4*)&Bf[base0 + 128];
            float4 b1a = *(const float4*)&Bf[base1];
            float4 b1b = *(const float4*)&Bf[base1 + 128];
            float b0[8] = {b0a.x,b0a.y,b0a.z,b0a.w, b0b.x,b0b.y,b0b.z,b0b.w};
            float b1[8] = {b1a.x,b1a.y,b1a.z,b1a.w, b1b.x,b1b.y,b1b.z,b1b.w};
#pragma unroll
            for (int nt = 0; nt < 8; ++nt) {
                unsigned u0 = __float_as_uint(b0[nt]);
                unsigned u1 = __float_as_uint(b1[nt]);
#pragma unroll
                for (int mt = 0; mt < 4; ++mt)
                    MMA(acc[mt][nt], af[mt], u0, u1);
            }
        }
        __syncthreads();
    }
#pragma unroll
    for (int mt = 0; mt < 4; ++mt)
#pragma unroll
        for (int nt = 0; nt < 8; ++nt) {
            int rm = row0 + m0 + mt*16 + gid;
            int cn = col0 + ncol*64 + nt*8 + tig*2;
            float b0 = g_bco[cn], b1v = g_bco[cn+1];
            *(float2*)(out + (size_t)rm*384 + cn) =
                make_float2(acc[mt][nt][0] + b0, acc[mt][nt][1] + b1v);
            *(float2*)(out + (size_t)(rm+8)*384 + cn) =
                make_float2(acc[mt][nt][2] + b0, acc[mt][nt][3] + b1v);
        }
}

extern "C" void kernel_launch(void* const* d_in, const int* in_sizes, int n_in,
                              void* d_out, int out_size) {
    const float* x   = (const float*)d_in[0];
    const float* Wc  = (const float*)d_in[1];
    const float* bc  = (const float*)d_in[2];
    const float* Wo  = (const float*)d_in[3];
    const float* bo  = (const float*)d_in[4];
    const float* W1h = (const float*)d_in[5];
    const float* b1h = (const float*)d_in[6];
    const float* W2h = (const float*)d_in[7];
    const float* b2h = (const float*)d_in[8];
    const float* W1w = (const float*)d_in[9];
    const float* b1w = (const float*)d_in[10];
    const float* W2w = (const float*)d_in[11];
    const float* b2w = (const float*)d_in[12];
    float* out = (float*)d_out;

    cudaFuncSetAttribute(apply_kernel, cudaFuncAttributeMaxDynamicSharedMemorySize, 53248);
    int gsz = (2*256*SA_P + 2*2048) * 4;   // 57344 B
    cudaFuncSetAttribute(gemm_kernel, cudaFuncAttributeMaxDynamicSharedMemorySize, gsz);

    prep_wco<<<dim3(12,12), dim3(32,32)>>>(Wc, Wo);
    prep_wot<<<dim3(12,12), dim3(32,32)>>>(Wo);
    prep_bco<<<1, 384>>>(Wo, bc, bo);
    prep_frag<<<288, 1024>>>();
    y4_kernel<<<512, 256>>>(x, W1h, b1h, W1w, b1w);
    attn_kernel<<<2048, 1024>>>(W2h, b2h, 0);
    attn_kernel<<<2048, 1024>>>(W2w, b2w, 1);
    apply_kernel<<<2048, 256, 53248>>>(x, 0);
    apply_kernel<<<2048, 256, 53248>>>(x, 1);
    gemm_kernel<<<dim3(3,256), 256, gsz>>>(x, out);
}

// round 16
// speedup vs baseline: 1.1803x; 1.1803x over previous
#include <cuda_runtime.h>
#include <cuda_fp16.h>
#include <cstdint>

#define BATCH 64
#define DDIM 384
#define NPIX (BATCH*32*32)

// ---------------- scratch ----------------
__device__ float g_y4[NPIX*4];
__device__ float g_ah[BATCH*32*1024];
__device__ float g_aw[BATCH*32*1024];
__device__ float g_T [NPIX*DDIM];
__device__ __half g_xh[NPIX*DDIM];
__device__ __half g_mxh[NPIX*DDIM];
__device__ float g_wcat[768*384];
__device__ unsigned g_wfragh[3*48*1024];   // fragment-ordered fp16 weights (half2 words)
__device__ float g_bco[384];

__device__ __forceinline__ unsigned long long pack2(float a) {
    unsigned long long r; asm("mov.b64 %0, {%1, %1};" : "=l"(r) : "f"(a)); return r;
}
#define FMA2(d,a,b) asm("fma.rn.f32x2 %0, %1, %2, %0;" : "+l"(d) : "l"(a), "l"(b))

// ---------------- prep ----------------
__global__ __launch_bounds__(1024) void prep_wco(const float* __restrict__ Wc,
                                                 const float* __restrict__ Wo) {
    __shared__ float sWo[32][33], sWc[32][33];
    int tx = threadIdx.x, ty = threadIdx.y;
    int o0 = blockIdx.x * 32, k0 = blockIdx.y * 32;
    float acc = 0.f;
    for (int dt = 0; dt < 12; ++dt) {
        sWo[ty][tx] = Wo[(o0 + ty)*384 + dt*32 + tx];
        sWc[ty][tx] = Wc[(dt*32 + ty)*384 + k0 + tx];
        __syncthreads();
#pragma unroll
        for (int dd = 0; dd < 32; ++dd) acc += sWo[ty][dd] * sWc[dd][tx];
        __syncthreads();
    }
    g_wcat[(k0 + tx)*384 + o0 + ty] = acc;
}

__global__ __launch_bounds__(1024) void prep_wot(const float* __restrict__ Wo) {
    __shared__ float s[32][33];
    int tx = threadIdx.x, ty = threadIdx.y;
    int o0 = blockIdx.x * 32, k0 = blockIdx.y * 32;
    s[ty][tx] = Wo[(o0 + ty)*384 + k0 + tx];
    __syncthreads();
    g_wcat[(384 + k0 + ty)*384 + o0 + tx] = s[tx][ty];
}

__global__ void prep_bco(const float* __restrict__ Wo, const float* __restrict__ bc,
                         const float* __restrict__ bo) {
    int o = threadIdx.x;
    if (o < 384) {
        float acc = bo[o];
        for (int k = 0; k < 384; ++k) acc += Wo[o*384 + k] * bc[k];
        g_bco[o] = acc;
    }
}

// B fragments for mma.sync.m16n8k16 (row.col), packed half2 per word.
// word idx = ((cblk*48+kt)*1024) + ncol*512 + (r*2+g)*128 + lane*4 + j
// lo = Wcat[k0][n], hi = Wcat[k0+1][n], k0 = kt*16+(lane&3)*2+r*8,
// n = cblk*128 + ncol*64 + (g*4+j)*8 + (lane>>2)
__global__ __launch_bounds__(1024) void prep_fragh() {
    int idx = blockIdx.x * 1024 + threadIdx.x;   // < 147456
    int j    = idx & 3;
    int lane = (idx >> 2) & 31;
    int g    = (idx >> 7) & 1;
    int r    = (idx >> 8) & 1;
    int ncol = (idx >> 9) & 1;
    int rest = idx >> 10;
    int kt = rest % 48, cblk = rest / 48;
    int k0 = kt*16 + (lane & 3)*2 + r*8;
    int n  = cblk*128 + ncol*64 + (g*4 + j)*8 + (lane >> 2);
    __half2 h = __floats2half2_rn(g_wcat[k0*384 + n], g_wcat[(k0+1)*384 + n]);
    g_wfragh[idx] = *(unsigned*)&h;
}

// ---------------- fused 1x1 convs + fp16 copy of x ----------------
__global__ __launch_bounds__(256) void y4_kernel(const float* __restrict__ x,
        const float* __restrict__ W1h, const float* __restrict__ b1h,
        const float* __restrict__ W1w, const float* __restrict__ b1w) {
    int lane = threadIdx.x & 31, warp = threadIdx.x >> 5;
    int dbase = lane * 12;
    float wh0[12], wh1[12], ww0[12], ww1[12];
#pragma unroll
    for (int u = 0; u < 12; ++u) {
        wh0[u] = __ldg(W1h + dbase + u);
        wh1[u] = __ldg(W1h + 384 + dbase + u);
        ww0[u] = __ldg(W1w + dbase + u);
        ww1[u] = __ldg(W1w + 384 + dbase + u);
    }
    float bh0 = __ldg(b1h), bh1 = __ldg(b1h+1), bw0 = __ldg(b1w), bw1 = __ldg(b1w+1);
    int pbase = blockIdx.x * 128 + warp * 16;
    for (int it = 0; it < 16; ++it) {
        int p = pbase + it;
        const float4* xr = (const float4*)(x + (size_t)p*384 + dbase);
        float4 v0 = xr[0], v1 = xr[1], v2 = xr[2];
        float xv[12] = {v0.x,v0.y,v0.z,v0.w, v1.x,v1.y,v1.z,v1.w, v2.x,v2.y,v2.z,v2.w};
        __half2* hd = (__half2*)(g_xh + (size_t)p*384 + dbase);
#pragma unroll
        for (int u = 0; u < 6; ++u) hd[u] = __floats2half2_rn(xv[2*u], xv[2*u+1]);
        float s0=0.f, s1=0.f, s2=0.f, s3=0.f;
#pragma unroll
        for (int u = 0; u < 12; ++u) {
            s0 += xv[u]*wh0[u]; s1 += xv[u]*wh1[u];
            s2 += xv[u]*ww0[u]; s3 += xv[u]*ww1[u];
        }
#pragma unroll
        for (int off = 16; off; off >>= 1) {
            s0 += __shfl_xor_sync(~0u, s0, off);
            s1 += __shfl_xor_sync(~0u, s1, off);
            s2 += __shfl_xor_sync(~0u, s2, off);
            s3 += __shfl_xor_sync(~0u, s3, off);
        }
        if (lane == 0)
            *(float4*)(g_y4 + (size_t)p*4) = make_float4(s0+bh0, s1+bh1, s2+bw0, s3+bw1);
    }
}

// ---------------- grouped-conv logits + softmax ----------------
__global__ __launch_bounds__(1024) void attn_kernel(const float* __restrict__ W2,
                                                    const float* __restrict__ b2, int mode) {
    __shared__ float ys[2][32];
    int blk = blockIdx.x, b = blk >> 5, s = blk & 31, t = threadIdx.x;
    if (t < 64) {
        int e = t >> 5, q = t & 31;
        int pix = mode ? ((b*32 + s)*32 + q) : ((b*32 + q)*32 + s);
        ys[e][q] = g_y4[(size_t)pix*4 + (mode ? 2 : 0) + e];
    }
    __syncthreads();
    int i = t >> 5, j = t & 31;
    int e = i >> 4;
    int cb = ((i >> 2) * 8) & 31;
    const float* wrow = W2 + (size_t)(i*32 + j)*8;
    float l = __ldg(b2 + i*32 + j);
#pragma unroll
    for (int cc = 0; cc < 8; ++cc) l += __ldg(wrow + cc) * ys[e][cb + cc];
    float m = l;
#pragma unroll
    for (int off = 16; off; off >>= 1) m = fmaxf(m, __shfl_xor_sync(~0u, m, off));
    float ex = expf(l - m), sum = ex;
#pragma unroll
    for (int off = 16; off; off >>= 1) sum += __shfl_xor_sync(~0u, sum, off);
    (mode ? g_aw : g_ah)[(size_t)blk*1024 + i*32 + j] = ex / sum;
}

// ---------------- attention apply ----------------
// mode 0: T[b,i,s,:] = sum_j Ah[b,s,i,j] x[b,j,s,:]        (f32 out)
// mode 1: mxh[b,s,i,:] = half(T[b,s,i,:] + sum_j Aw[b,s,i,j] x[b,s,j,:])
__global__ __launch_bounds__(256) void apply_kernel(const float* __restrict__ x, int mode) {
    extern __shared__ float sm[];
    float* xs = sm;            // [32][384]
    float* as = sm + 32*384;   // [1024]
    int blk = blockIdx.x, b = blk >> 5, s = blk & 31, t = threadIdx.x;
    size_t rowbase, rowstride;
    if (mode == 0) { rowbase = ((size_t)b*1024 + s)*384;    rowstride = 32*384; }
    else           { rowbase = ((size_t)b*1024 + s*32)*384; rowstride = 384; }
    for (int l = t; l < 3072; l += 256) {
        int r = l / 96, c4 = l % 96;
        *(float4*)&xs[r*384 + c4*4] = *(const float4*)(x + rowbase + (size_t)r*rowstride + c4*4);
    }
    const float* attn = (mode ? g_aw : g_ah) + (size_t)blk*1024;
    for (int l = t; l < 1024; l += 256) as[l] = attn[l];
    __syncthreads();
    int w = t >> 5, lane = t & 31;
    unsigned long long acc[4][6];
#pragma unroll
    for (int ii = 0; ii < 4; ++ii)
#pragma unroll
        for (int q = 0; q < 6; ++q) acc[ii][q] = 0ull;
#pragma unroll 4
    for (int j = 0; j < 32; ++j) {
        ulonglong2 xv[3];
#pragma unroll
        for (int c = 0; c < 3; ++c)
            xv[c] = *(ulonglong2*)&xs[j*384 + (lane + 32*c)*4];
#pragma unroll
        for (int ii = 0; ii < 4; ++ii) {
            unsigned long long av = pack2(as[(w + 8*ii)*32 + j]);
#pragma unroll
            for (int c = 0; c < 3; ++c) {
                FMA2(acc[ii][2*c],   av, xv[c].x);
                FMA2(acc[ii][2*c+1], av, xv[c].y);
            }
        }
    }
#pragma unroll
    for (int ii = 0; ii < 4; ++ii) {
        int i = w + 8*ii;
#pragma unroll
        for (int c = 0; c < 3; ++c) {
            int d = (lane + 32*c)*4;
            float2 u0 = *(float2*)&acc[ii][2*c];
            float2 u1 = *(float2*)&acc[ii][2*c+1];
            if (mode == 0) {
                *(float4*)(g_T + ((size_t)(b*32 + i)*32 + s)*384 + d) =
                    make_float4(u0.x, u0.y, u1.x, u1.y);
            } else {
                size_t o = ((size_t)b*1024 + s*32 + i)*384 + d;
                float4 tv = *(const float4*)(g_T + o);
                __half2 h0 = __floats2half2_rn(u0.x+tv.x, u0.y+tv.y);
                __half2 h1 = __floats2half2_rn(u1.x+tv.z, u1.y+tv.w);
                uint2 pk; pk.x = *(unsigned*)&h0; pk.y = *(unsigned*)&h1;
                *(uint2*)(g_mxh + o) = pk;
            }
        }
    }
}

// ---------------- big GEMM (fp16 mma.sync m16n8k16) ----------------
// out[p][o] = sum_k [x|mx][p][k] * Wcat[k][o] + bco[o]
// BM=256, BN=128, 8 warps, warp tile 64x64, BK=16 per stage, 48 stages.
#define A_WORDS 5120           // 256 rows * 20 words (40 halfs incl. pad)
#define B_WORDS 1024
#define STG_WORDS (A_WORDS + B_WORDS)
#define MMAH(d, a, b0, b1) \
    asm("mma.sync.aligned.m16n8k16.row.col.f32.f16.f16.f32 " \
        "{%0,%1,%2,%3}, {%4,%5,%6,%7}, {%8,%9}, {%0,%1,%2,%3};" \
        : "+f"(d[0]), "+f"(d[1]), "+f"(d[2]), "+f"(d[3]) \
        : "r"(a[0]), "r"(a[1]), "r"(a[2]), "r"(a[3]), "r"(b0), "r"(b1))

__global__ __launch_bounds__(256) void gemm_f16(float* __restrict__ out) {
    extern __shared__ __align__(16) unsigned gsw[];
    int t = threadIdx.x;
    int row0 = blockIdx.y * 256, cblk = blockIdx.x, col0 = cblk * 128;
    unsigned sbase = (unsigned)__cvta_generic_to_shared(gsw);
    auto load_stage = [&](int kt, int buf) {
        const __half* Ah = (kt < 24) ? g_xh : g_mxh;
        int koff = (kt < 24) ? kt*16 : kt*16 - 384;
        unsigned abase = sbase + buf*STG_WORDS*4;
#pragma unroll
        for (int q = 0; q < 2; ++q) {
            int c = t + 256*q;            // 512 A chunks of 16B
            int r = c >> 1, seg = c & 1;
            const __half* src = Ah + (size_t)(row0 + r)*384 + koff + seg*8;
            unsigned dst = abase + (unsigned)(r*80 + seg*16);
            asm volatile("cp.async.ca.shared.global [%0], [%1], 16;" :: "r"(dst), "l"(src));
        }
        const unsigned* srcB = g_wfragh + ((size_t)cblk*48 + kt)*1024 + t*4;
        unsigned dstB = abase + A_WORDS*4 + t*16;
        asm volatile("cp.async.ca.shared.global [%0], [%1], 16;" :: "r"(dstB), "l"(srcB));
        asm volatile("cp.async.commit_group;" ::: "memory");
    };
    int lane = t & 31, w = t >> 5;
    int gid = lane >> 2, tig = lane & 3;
    int m0 = (w & 3) * 64, ncol = w >> 2;
    float acc[4][8][4];
#pragma unroll
    for (int mt = 0; mt < 4; ++mt)
#pragma unroll
        for (int nt = 0; nt < 8; ++nt)
#pragma unroll
            for (int q = 0; q < 4; ++q) acc[mt][nt][q] = 0.f;
    load_stage(0, 0);
    for (int kt = 0; kt < 48; ++kt) {
        int buf = kt & 1;
        if (kt + 1 < 48) {
            load_stage(kt + 1, buf ^ 1);
            asm volatile("cp.async.wait_group 1;" ::: "memory");
        } else {
            asm volatile("cp.async.wait_group 0;" ::: "memory");
        }
        __syncthreads();
        const unsigned* Aw = gsw + buf*STG_WORDS;
        const unsigned* Bw = Aw + A_WORDS;
        unsigned af[4][4];
#pragma unroll
        for (int mt = 0; mt < 4; ++mt) {
            int rm = m0 + mt*16 + gid;
            af[mt][0] = Aw[rm*20 + tig];
            af[mt][1] = Aw[(rm+8)*20 + tig];
            af[mt][2] = Aw[rm*20 + tig + 4];
            af[mt][3] = Aw[(rm+8)*20 + tig + 4];
        }
        const unsigned* Bn = Bw + ncol*512 + lane*4;
        uint4 q00 = *(const uint4*)(Bn);         // b0, nt 0..3
        uint4 q01 = *(const uint4*)(Bn + 128);   // b0, nt 4..7
        uint4 q10 = *(const uint4*)(Bn + 256);   // b1, nt 0..3
        uint4 q11 = *(const uint4*)(Bn + 384);   // b1, nt 4..7
        unsigned b0[8] = {q00.x,q00.y,q00.z,q00.w, q01.x,q01.y,q01.z,q01.w};
        unsigned b1[8] = {q10.x,q10.y,q10.z,q10.w, q11.x,q11.y,q11.z,q11.w};
#pragma unroll
        for (int nt = 0; nt < 8; ++nt)
#pragma unroll
            for (int mt = 0; mt < 4; ++mt)
                MMAH(acc[mt][nt], af[mt], b0[nt], b1[nt]);
        __syncthreads();
    }
#pragma unroll
    for (int mt = 0; mt < 4; ++mt)
#pragma unroll
        for (int nt = 0; nt < 8; ++nt) {
            int rm = row0 + m0 + mt*16 + gid;
            int cn = col0 + ncol*64 + nt*8 + tig*2;
            float b0v = g_bco[cn], b1v = g_bco[cn+1];
            *(float2*)(out + (size_t)rm*384 + cn) =
                make_float2(acc[mt][nt][0] + b0v, acc[mt][nt][1] + b1v);
            *(float2*)(out + (size_t)(rm+8)*384 + cn) =
                make_float2(acc[mt][nt][2] + b0v, acc[mt][nt][3] + b1v);
        }
}

extern "C" void kernel_launch(void* const* d_in, const int* in_sizes, int n_in,
                              void* d_out, int out_size) {
    const float* x   = (const float*)d_in[0];
    const float* Wc  = (const float*)d_in[1];
    const float* bc  = (const float*)d_in[2];
    const float* Wo  = (const float*)d_in[3];
    const float* bo  = (const float*)d_in[4];
    const float* W1h = (const float*)d_in[5];
    const float* b1h = (const float*)d_in[6];
    const float* W2h = (const float*)d_in[7];
    const float* b2h = (const float*)d_in[8];
    const float* W1w = (const float*)d_in[9];
    const float* b1w = (const float*)d_in[10];
    const float* W2w = (const float*)d_in[11];
    const float* b2w = (const float*)d_in[12];
    float* out = (float*)d_out;

    cudaFuncSetAttribute(apply_kernel, cudaFuncAttributeMaxDynamicSharedMemorySize, 53248);
    int gsz = 2*STG_WORDS*4;   // 49152 B
    cudaFuncSetAttribute(gemm_f16, cudaFuncAttributeMaxDynamicSharedMemorySize, gsz);

    prep_wco<<<dim3(12,12), dim3(32,32)>>>(Wc, Wo);
    prep_wot<<<dim3(12,12), dim3(32,32)>>>(Wo);
    prep_bco<<<1, 384>>>(Wo, bc, bo);
    prep_fragh<<<144, 1024>>>();
    y4_kernel<<<512, 256>>>(x, W1h, b1h, W1w, b1w);
    attn_kernel<<<2048, 1024>>>(W2h, b2h, 0);
    attn_kernel<<<2048, 1024>>>(W2w, b2w, 1);
    apply_kernel<<<2048, 256, 53248>>>(x, 0);
    apply_kernel<<<2048, 256, 53248>>>(x, 1);
    gemm_f16<<<dim3(3,256), 256, gsz>>>(out);
}

// round 17
// speedup vs baseline: 1.2917x; 1.0944x over previous
#include <cuda_runtime.h>
#include <cuda_fp16.h>
#include <cstdint>

#define BATCH 64
#define DDIM 384
#define NPIX (BATCH*32*32)

// ---------------- scratch ----------------
__device__ float g_y4[NPIX*4];
__device__ float g_ah[BATCH*32*1024];
__device__ float g_aw[BATCH*32*1024];
__device__ float g_T [NPIX*DDIM];
__device__ __half g_xh[NPIX*DDIM];
__device__ __half g_mxh[NPIX*DDIM];
__device__ float g_wcat[768*384];
__device__ unsigned g_wfragh[3*24*2048];   // fragment-ordered fp16 weights (half2 words)
__device__ float g_bco[384];

__device__ __forceinline__ unsigned long long pack2(float a) {
    unsigned long long r; asm("mov.b64 %0, {%1, %1};" : "=l"(r) : "f"(a)); return r;
}
#define FMA2(d,a,b) asm("fma.rn.f32x2 %0, %1, %2, %0;" : "+l"(d) : "l"(a), "l"(b))

// ---------------- prep ----------------
__global__ __launch_bounds__(1024) void prep_wco(const float* __restrict__ Wc,
                                                 const float* __restrict__ Wo) {
    __shared__ float sWo[32][33], sWc[32][33];
    int tx = threadIdx.x, ty = threadIdx.y;
    int o0 = blockIdx.x * 32, k0 = blockIdx.y * 32;
    float acc = 0.f;
    for (int dt = 0; dt < 12; ++dt) {
        sWo[ty][tx] = Wo[(o0 + ty)*384 + dt*32 + tx];
        sWc[ty][tx] = Wc[(dt*32 + ty)*384 + k0 + tx];
        __syncthreads();
#pragma unroll
        for (int dd = 0; dd < 32; ++dd) acc += sWo[ty][dd] * sWc[dd][tx];
        __syncthreads();
    }
    g_wcat[(k0 + tx)*384 + o0 + ty] = acc;
}

__global__ __launch_bounds__(1024) void prep_wot(const float* __restrict__ Wo) {
    __shared__ float s[32][33];
    int tx = threadIdx.x, ty = threadIdx.y;
    int o0 = blockIdx.x * 32, k0 = blockIdx.y * 32;
    s[ty][tx] = Wo[(o0 + ty)*384 + k0 + tx];
    __syncthreads();
    g_wcat[(384 + k0 + ty)*384 + o0 + tx] = s[tx][ty];
}

__global__ void prep_bco(const float* __restrict__ Wo, const float* __restrict__ bc,
                         const float* __restrict__ bo) {
    int o = threadIdx.x;
    if (o < 384) {
        float acc = bo[o];
        for (int k = 0; k < 384; ++k) acc += Wo[o*384 + k] * bc[k];
        g_bco[o] = acc;
    }
}

// B fragments for mma.sync.m16n8k16 (row.col), packed half2 per word.
// per (cblk, kt32): 2048 words: [kk(2)][ncol(4)][r(2)][lane(32)][nt(4)]
// k0 = kt*32 + kk*16 + (lane&3)*2 + r*8
// n  = cblk*128 + ncol*32 + nt*8 + (lane>>2)
// value = half2(Wcat[k0][n], Wcat[k0+1][n])
__global__ __launch_bounds__(1024) void prep_fragh() {
    int idx = blockIdx.x * 1024 + threadIdx.x;   // < 147456
    int nt   = idx & 3;
    int lane = (idx >> 2) & 31;
    int r    = (idx >> 7) & 1;
    int ncol = (idx >> 8) & 3;
    int kk   = (idx >> 10) & 1;
    int rest = idx >> 11;
    int kt = rest % 24, cblk = rest / 24;
    int k0 = kt*32 + kk*16 + (lane & 3)*2 + r*8;
    int n  = cblk*128 + ncol*32 + nt*8 + (lane >> 2);
    __half2 h = __floats2half2_rn(g_wcat[k0*384 + n], g_wcat[(k0+1)*384 + n]);
    g_wfragh[idx] = *(unsigned*)&h;
}

// ---------------- fused 1x1 convs + fp16 copy of x ----------------
__global__ __launch_bounds__(256) void y4_kernel(const float* __restrict__ x,
        const float* __restrict__ W1h, const float* __restrict__ b1h,
        const float* __restrict__ W1w, const float* __restrict__ b1w) {
    int lane = threadIdx.x & 31, warp = threadIdx.x >> 5;
    int dbase = lane * 12;
    float wh0[12], wh1[12], ww0[12], ww1[12];
#pragma unroll
    for (int u = 0; u < 12; ++u) {
        wh0[u] = __ldg(W1h + dbase + u);
        wh1[u] = __ldg(W1h + 384 + dbase + u);
        ww0[u] = __ldg(W1w + dbase + u);
        ww1[u] = __ldg(W1w + 384 + dbase + u);
    }
    float bh0 = __ldg(b1h), bh1 = __ldg(b1h+1), bw0 = __ldg(b1w), bw1 = __ldg(b1w+1);
    int pbase = blockIdx.x * 128 + warp * 16;
    for (int it = 0; it < 16; ++it) {
        int p = pbase + it;
        const float4* xr = (const float4*)(x + (size_t)p*384 + dbase);
        float4 v0 = xr[0], v1 = xr[1], v2 = xr[2];
        float xv[12] = {v0.x,v0.y,v0.z,v0.w, v1.x,v1.y,v1.z,v1.w, v2.x,v2.y,v2.z,v2.w};
        __half2* hd = (__half2*)(g_xh + (size_t)p*384 + dbase);
#pragma unroll
        for (int u = 0; u < 6; ++u) hd[u] = __floats2half2_rn(xv[2*u], xv[2*u+1]);
        float s0=0.f, s1=0.f, s2=0.f, s3=0.f;
#pragma unroll
        for (int u = 0; u < 12; ++u) {
            s0 += xv[u]*wh0[u]; s1 += xv[u]*wh1[u];
            s2 += xv[u]*ww0[u]; s3 += xv[u]*ww1[u];
        }
#pragma unroll
        for (int off = 16; off; off >>= 1) {
            s0 += __shfl_xor_sync(~0u, s0, off);
            s1 += __shfl_xor_sync(~0u, s1, off);
            s2 += __shfl_xor_sync(~0u, s2, off);
            s3 += __shfl_xor_sync(~0u, s3, off);
        }
        if (lane == 0)
            *(float4*)(g_y4 + (size_t)p*4) = make_float4(s0+bh0, s1+bh1, s2+bw0, s3+bw1);
    }
}

// ---------------- grouped-conv logits + softmax ----------------
__global__ __launch_bounds__(1024) void attn_kernel(const float* __restrict__ W2,
                                                    const float* __restrict__ b2, int mode) {
    __shared__ float ys[2][32];
    int blk = blockIdx.x, b = blk >> 5, s = blk & 31, t = threadIdx.x;
    if (t < 64) {
        int e = t >> 5, q = t & 31;
        int pix = mode ? ((b*32 + s)*32 + q) : ((b*32 + q)*32 + s);
        ys[e][q] = g_y4[(size_t)pix*4 + (mode ? 2 : 0) + e];
    }
    __syncthreads();
    int i = t >> 5, j = t & 31;
    int e = i >> 4;
    int cb = ((i >> 2) * 8) & 31;
    const float* wrow = W2 + (size_t)(i*32 + j)*8;
    float l = __ldg(b2 + i*32 + j);
#pragma unroll
    for (int cc = 0; cc < 8; ++cc) l += __ldg(wrow + cc) * ys[e][cb + cc];
    float m = l;
#pragma unroll
    for (int off = 16; off; off >>= 1) m = fmaxf(m, __shfl_xor_sync(~0u, m, off));
    float ex = expf(l - m), sum = ex;
#pragma unroll
    for (int off = 16; off; off >>= 1) sum += __shfl_xor_sync(~0u, sum, off);
    (mode ? g_aw : g_ah)[(size_t)blk*1024 + i*32 + j] = ex / sum;
}

// ---------------- attention apply ----------------
__global__ __launch_bounds__(256) void apply_kernel(const float* __restrict__ x, int mode) {
    extern __shared__ float sm[];
    float* xs = sm;            // [32][384]
    float* as = sm + 32*384;   // [1024]
    int blk = blockIdx.x, b = blk >> 5, s = blk & 31, t = threadIdx.x;
    size_t rowbase, rowstride;
    if (mode == 0) { rowbase = ((size_t)b*1024 + s)*384;    rowstride = 32*384; }
    else           { rowbase = ((size_t)b*1024 + s*32)*384; rowstride = 384; }
    for (int l = t; l < 3072; l += 256) {
        int r = l / 96, c4 = l % 96;
        *(float4*)&xs[r*384 + c4*4] = *(const float4*)(x + rowbase + (size_t)r*rowstride + c4*4);
    }
    const float* attn = (mode ? g_aw : g_ah) + (size_t)blk*1024;
    for (int l = t; l < 1024; l += 256) as[l] = attn[l];
    __syncthreads();
    int w = t >> 5, lane = t & 31;
    unsigned long long acc[4][6];
#pragma unroll
    for (int ii = 0; ii < 4; ++ii)
#pragma unroll
        for (int q = 0; q < 6; ++q) acc[ii][q] = 0ull;
#pragma unroll 4
    for (int j = 0; j < 32; ++j) {
        ulonglong2 xv[3];
#pragma unroll
        for (int c = 0; c < 3; ++c)
            xv[c] = *(ulonglong2*)&xs[j*384 + (lane + 32*c)*4];
#pragma unroll
        for (int ii = 0; ii < 4; ++ii) {
            unsigned long long av = pack2(as[(w + 8*ii)*32 + j]);
#pragma unroll
            for (int c = 0; c < 3; ++c) {
                FMA2(acc[ii][2*c],   av, xv[c].x);
                FMA2(acc[ii][2*c+1], av, xv[c].y);
            }
        }
    }
#pragma unroll
    for (int ii = 0; ii < 4; ++ii) {
        int i = w + 8*ii;
#pragma unroll
        for (int c = 0; c < 3; ++c) {
            int d = (lane + 32*c)*4;
            float2 u0 = *(float2*)&acc[ii][2*c];
            float2 u1 = *(float2*)&acc[ii][2*c+1];
            if (mode == 0) {
                *(float4*)(g_T + ((size_t)(b*32 + i)*32 + s)*384 + d) =
                    make_float4(u0.x, u0.y, u1.x, u1.y);
            } else {
                size_t o = ((size_t)b*1024 + s*32 + i)*384 + d;
                float4 tv = *(const float4*)(g_T + o);
                __half2 h0 = __floats2half2_rn(u0.x+tv.x, u0.y+tv.y);
                __half2 h1 = __floats2half2_rn(u1.x+tv.z, u1.y+tv.w);
                uint2 pk; pk.x = *(unsigned*)&h0; pk.y = *(unsigned*)&h1;
                *(uint2*)(g_mxh + o) = pk;
            }
        }
    }
}

// ---------------- big GEMM (fp16 mma.sync m16n8k16) ----------------
// BM=256, BN=128, 512 threads / 16 warps, warp tile 64x32, BK=32, 24 stages,
// 3-stage cp.async ring, ldmatrix A, one __syncthreads per stage.
#define A_STG_B 20480          // 256 rows * 80 B (32 halfs + 16B pad)
#define B_STG_B 8192           // 2048 words
#define STG_B   (A_STG_B + B_STG_B)
#define MMAH(d, a, b0, b1) \
    asm("mma.sync.aligned.m16n8k16.row.col.f32.f16.f16.f32 " \
        "{%0,%1,%2,%3}, {%4,%5,%6,%7}, {%8,%9}, {%0,%1,%2,%3};" \
        : "+f"(d[0]), "+f"(d[1]), "+f"(d[2]), "+f"(d[3]) \
        : "r"(a[0]), "r"(a[1]), "r"(a[2]), "r"(a[3]), "r"(b0), "r"(b1))

__global__ __launch_bounds__(512) void gemm_f16(float* __restrict__ out) {
    extern __shared__ __align__(16) char gsm[];
    int t = threadIdx.x;
    int row0 = blockIdx.y * 256, cblk = blockIdx.x, col0 = cblk * 128;
    unsigned sbase = (unsigned)__cvta_generic_to_shared(gsm);
    auto load_stage = [&](int s, int buf) {
        const __half* Ah = (s < 12) ? g_xh : g_mxh;
        int koff = (s < 12) ? s*32 : s*32 - 384;
        unsigned abase = sbase + buf*STG_B;
#pragma unroll
        for (int q = 0; q < 2; ++q) {
            int c = t + 512*q;            // 1024 A chunks of 16B
            int r = c >> 2, seg = c & 3;
            const __half* src = Ah + (size_t)(row0 + r)*384 + koff + seg*8;
            unsigned dst = abase + (unsigned)(r*80 + seg*16);
            asm volatile("cp.async.ca.shared.global [%0], [%1], 16;" :: "r"(dst), "l"(src));
        }
        const unsigned* srcB = g_wfragh + ((size_t)cblk*24 + s)*2048 + t*4;
        unsigned dstB = abase + A_STG_B + t*16;
        asm volatile("cp.async.ca.shared.global [%0], [%1], 16;" :: "r"(dstB), "l"(srcB));
        asm volatile("cp.async.commit_group;" ::: "memory");
    };
    int lane = t & 31, w = t >> 5;
    int gid = lane >> 2, tig = lane & 3;
    int m0 = (w & 3) * 64, ncol = w >> 2;
    // ldmatrix lane address components
    int lm_row = (lane & 7) + ((lane >> 3) & 1) * 8;  // row within 16
    int lm_k   = (lane >> 4) * 8;                     // k-half select
    float acc[4][4][4];
#pragma unroll
    for (int mt = 0; mt < 4; ++mt)
#pragma unroll
        for (int nt = 0; nt < 4; ++nt)
#pragma unroll
            for (int q = 0; q < 4; ++q) acc[mt][nt][q] = 0.f;
    load_stage(0, 0);
    load_stage(1, 1);
#pragma unroll 1
    for (int s = 0; s < 24; ++s) {
        int buf = s % 3;
        if (s < 23) { asm volatile("cp.async.wait_group 1;" ::: "memory"); }
        else        { asm volatile("cp.async.wait_group 0;" ::: "memory"); }
        __syncthreads();
        if (s + 2 < 24) load_stage(s + 2, (s + 2) % 3);
        unsigned abase = sbase + buf*STG_B;
        unsigned bgen  = buf*STG_B + A_STG_B;
        const unsigned* Bw = (const unsigned*)(gsm + bgen);
#pragma unroll
        for (int kk = 0; kk < 2; ++kk) {
            unsigned af[4][4];
#pragma unroll
            for (int mt = 0; mt < 4; ++mt) {
                unsigned addr = abase
                    + (unsigned)((m0 + mt*16 + lm_row)*80 + (kk*16 + lm_k)*2);
                asm volatile("ldmatrix.sync.aligned.m8n8.x4.shared.b16 {%0,%1,%2,%3}, [%4];"
                    : "=r"(af[mt][0]), "=r"(af[mt][1]), "=r"(af[mt][2]), "=r"(af[mt][3])
                    : "r"(addr));
            }
            const unsigned* Bn = Bw + kk*1024 + ncol*256 + lane*4;
            uint4 q0 = *(const uint4*)(Bn);         // b0 for nt 0..3
            uint4 q1 = *(const uint4*)(Bn + 128);   // b1 for nt 0..3
            unsigned b0[4] = {q0.x, q0.y, q0.z, q0.w};
            unsigned b1[4] = {q1.x, q1.y, q1.z, q1.w};
#pragma unroll
            for (int nt = 0; nt < 4; ++nt)
#pragma unroll
                for (int mt = 0; mt < 4; ++mt)
                    MMAH(acc[mt][nt], af[mt], b0[nt], b1[nt]);
        }
    }
#pragma unroll
    for (int mt = 0; mt < 4; ++mt)
#pragma unroll
        for (int nt = 0; nt < 4; ++nt) {
            int rm = row0 + m0 + mt*16 + gid;
            int cn = col0 + ncol*32 + nt*8 + tig*2;
            float b0v = g_bco[cn], b1v = g_bco[cn+1];
            *(float2*)(out + (size_t)rm*384 + cn) =
                make_float2(acc[mt][nt][0] + b0v, acc[mt][nt][1] + b1v);
            *(float2*)(out + (size_t)(rm+8)*384 + cn) =
                make_float2(acc[mt][nt][2] + b0v, acc[mt][nt][3] + b1v);
        }
}

extern "C" void kernel_launch(void* const* d_in, const int* in_sizes, int n_in,
                              void* d_out, int out_size) {
    const float* x   = (const float*)d_in[0];
    const float* Wc  = (const float*)d_in[1];
    const float* bc  = (const float*)d_in[2];
    const float* Wo  = (const float*)d_in[3];
    const float* bo  = (const float*)d_in[4];
    const float* W1h = (const float*)d_in[5];
    const float* b1h = (const float*)d_in[6];
    const float* W2h = (const float*)d_in[7];
    const float* b2h = (const float*)d_in[8];
    const float* W1w = (const float*)d_in[9];
    const float* b1w = (const float*)d_in[10];
    const float* W2w = (const float*)d_in[11];
    const float* b2w = (const float*)d_in[12];
    float* out = (float*)d_out;

    cudaFuncSetAttribute(apply_kernel, cudaFuncAttributeMaxDynamicSharedMemorySize, 53248);
    int gsz = 3*STG_B;   // 86016 B
    cudaFuncSetAttribute(gemm_f16, cudaFuncAttributeMaxDynamicSharedMemorySize, gsz);

    prep_wco<<<dim3(12,12), dim3(32,32)>>>(Wc, Wo);
    prep_wot<<<dim3(12,12), dim3(32,32)>>>(Wo);
    prep_bco<<<1, 384>>>(Wo, bc, bo);
    prep_fragh<<<144, 1024>>>();
    y4_kernel<<<512, 256>>>(x, W1h, b1h, W1w, b1w);
    attn_kernel<<<2048, 1024>>>(W2h, b2h, 0);
    attn_kernel<<<2048, 1024>>>(W2w, b2w, 1);
    apply_kernel<<<2048, 256, 53248>>>(x, 0);
    apply_kernel<<<2048, 256, 53248>>>(x, 1);
    gemm_f16<<<dim3(3,256), 512, gsz>>>(out);
}